// round 3
// baseline (speedup 1.0000x reference)
#include <cuda_runtime.h>
#include <cuda_bf16.h>

#define NN 2048
#define KK 4095              // number of anti-diagonals = 2N-1
#define BIGF 1e10f
#define DSK_STRIDE ((size_t)NN)
#define DSK_MAT ((size_t)KK * (size_t)NN)   // 8,386,560 floats per matrix

// ---------------- device scratch (no allocations allowed) ----------------
__device__ float  g_dsk[3 * KK * NN];   // ~100.6 MB, diagonal-major D for xy/xx/yy
__device__ float  g_norms[2 * NN];      // row norms of a (first 2048) and b (next 2048)
__device__ double g_idm[2];             // idm_a, idm_b accumulators
__device__ float  g_sdtw[3];            // softdtw(xy), softdtw(xx), softdtw(yy)

// ---------------- fast math helpers ----------------
__device__ __forceinline__ float ex2f(float x) {
    float y; asm("ex2.approx.ftz.f32 %0, %1;" : "=f"(y) : "f"(x)); return y;
}
__device__ __forceinline__ float lg2f_(float x) {
    float y; asm("lg2.approx.f32 %0, %1;" : "=f"(y) : "f"(x)); return y;
}

// softmin_gamma(v0,v1,v2) with gamma=0.1:
//   m - gamma*log( exp((m-v0)/g) + exp((m-v1)/g) + exp((m-v2)/g) )
// The min term's exp is exactly 1, so only 2 ex2 + 1 lg2 are needed.
#define C_EXP 14.4269504088896340f   /* 10 * log2(e)  (1/gamma = 10) */
#define C_LOG 0.0693147180559945f    /* 0.1 * ln(2) */
__device__ __forceinline__ float softmin3(float v0, float v1, float v2) {
    float m = fminf(fminf(v0, v1), v2);
    float p = (v0 == m) ? v1 : v0;
    float q = (v0 == m || v1 == m) ? v2 : v1;
    float e1 = ex2f((m - p) * C_EXP);
    float e2 = ex2f((m - q) * C_EXP);
    float s  = 1.0f + e1 + e2;
    return m - C_LOG * lg2f_(s);
}

// ---------------- row norms + accumulator init ----------------
__global__ void norms_kernel(const float* __restrict__ a, const float* __restrict__ b) {
    if (blockIdx.x == 0 && threadIdx.x == 0) { g_idm[0] = 0.0; g_idm[1] = 0.0; }
    int w    = blockIdx.x * (blockDim.x >> 5) + (threadIdx.x >> 5);
    int lane = threadIdx.x & 31;
    if (w >= 2 * NN) return;
    const float* src = (w < NN) ? (a + (size_t)w * 128) : (b + (size_t)(w - NN) * 128);
    float s = 0.0f;
#pragma unroll
    for (int q = 0; q < 4; q++) { float v = src[lane + 32 * q]; s = fmaf(v, v, s); }
#pragma unroll
    for (int off = 16; off; off >>= 1) s += __shfl_xor_sync(0xffffffffu, s, off);
    if (lane == 0) g_norms[w] = s;
}

// ---------------- pairwise sqdist GEMM: writes diagonal-major D, fuses idm ----------------
// Tile 64x64, K chunked by 64. 256 threads, 4x4 microtile per thread.
__global__ void __launch_bounds__(256) pairdist_kernel(const float* __restrict__ a,
                                                       const float* __restrict__ b) {
    __shared__ float pool[2 * 64 * 65];   // 33,280 B
    float* xsT = pool;                    // [kk][ii], stride 65 (conflict-free)
    float* ysT = pool + 64 * 65;

    const int z = blockIdx.z;             // 0: (a,b)  1: (a,a)  2: (b,b)
    const float* X  = (z == 2) ? b : a;
    const float* Y  = (z == 0) ? b : ((z == 1) ? a : b);
    const float* xn = g_norms + ((z == 2) ? NN : 0);
    const float* yn = g_norms + ((z == 1) ? 0 : NN);

    const int i0 = blockIdx.y * 64, j0 = blockIdx.x * 64;
    const int tid = threadIdx.x;
    const int tx = tid & 15, ty = tid >> 4;

    float acc[4][4];
#pragma unroll
    for (int r = 0; r < 4; r++)
#pragma unroll
        for (int c = 0; c < 4; c++) acc[r][c] = 0.0f;

    for (int kc = 0; kc < 128; kc += 64) {
        const int kk = tid & 63, ib = tid >> 6;
#pragma unroll
        for (int ii = ib; ii < 64; ii += 4) {
            xsT[kk * 65 + ii] = X[(size_t)(i0 + ii) * 128 + kc + kk];
            ysT[kk * 65 + ii] = Y[(size_t)(j0 + ii) * 128 + kc + kk];
        }
        __syncthreads();
#pragma unroll 4
        for (int k2 = 0; k2 < 64; ++k2) {
            float ra[4], rb[4];
#pragma unroll
            for (int r = 0; r < 4; r++) ra[r] = xsT[k2 * 65 + ty * 4 + r];
#pragma unroll
            for (int c = 0; c < 4; c++) rb[c] = ysT[k2 * 65 + tx * 4 + c];
#pragma unroll
            for (int r = 0; r < 4; r++)
#pragma unroll
                for (int c = 0; c < 4; c++) acc[r][c] = fmaf(ra[r], rb[c], acc[r][c]);
        }
        __syncthreads();
    }

    // Epilogue: D = max(xn + yn - 2*dot, 0); stage into smem (stride 66) + idm
    float xnv[4], ynv[4];
#pragma unroll
    for (int r = 0; r < 4; r++) xnv[r] = xn[i0 + ty * 4 + r];
#pragma unroll
    for (int c = 0; c < 4; c++) ynv[c] = yn[j0 + tx * 4 + c];

    float* ds = pool;                     // reuse; 64 x 66 floats
    float lsum = 0.0f;
    const float inv_n = 1.0f / 2048.0f;
    const float thr   = 10.0f / 2048.0f;  // SIGMA / seq_len (exact in fp32)
#pragma unroll
    for (int r = 0; r < 4; r++) {
#pragma unroll
        for (int c = 0; c < 4; c++) {
            float d = fmaxf(xnv[r] + ynv[c] - 2.0f * acc[r][c], 0.0f);
            ds[(ty * 4 + r) * 66 + tx * 4 + c] = d;
            if (z) {
                int ig = i0 + ty * 4 + r, jg = j0 + tx * 4 + c;
                float gd   = (float)(ig - jg) * inv_n;       // == i/2048 - j/2048 exactly
                float wgt  = fmaf(gd, gd, 1.0f);
                float diff = fabsf(gd) - thr;
                float prob = fmaxf(2.0f - d, 0.0f);
                lsum += (diff > 0.0f) ? (wgt * prob) : d;
            }
        }
    }
    if (z) {
#pragma unroll
        for (int off = 16; off; off >>= 1) lsum += __shfl_xor_sync(0xffffffffu, lsum, off);
        if ((tid & 31) == 0) atomicAdd(&g_idm[z - 1], (double)lsum);
    }
    __syncthreads();  // ds fully written (and all smem reads done) before diag write-out

    // Diagonal-major write-out: contiguous segments per tile diagonal (coalesced)
    float* dst = g_dsk + (size_t)z * DSK_MAT + (size_t)(i0 + j0) * DSK_STRIDE + i0;
    const int w = tid >> 5, lane = tid & 31;
    for (int d = w; d < 127; d += 8) {
        int lo = max(0, d - 63), hi = min(63, d);
        for (int e = lo + lane; e <= hi; e += 32) {
            dst[(size_t)d * DSK_STRIDE + e] = ds[e * 66 + (d - e)];
        }
    }
}

// ---------------- softDTW wavefront: 1 CTA per matrix, 1024 threads, 2 elems/thread ----------------
__global__ void __launch_bounds__(1024, 1) softdtw_kernel() {
    const int z = blockIdx.x;
    const float* __restrict__ dsk = g_dsk + (size_t)z * DSK_MAT;
    const int t = threadIdx.x;
    const int lane = t & 31, w = t >> 5;
    const int i0 = 2 * t, i1 = i0 + 1;

    __shared__ float wb[3][32];           // warp-boundary ring (r_k high-element per warp)
    if (t < 32) { wb[0][t] = BIGF; wb[2][t] = BIGF; }   // r_0 highs, r_{-1} highs

    // register-resident rows: a*, b* = (low, high) elements of r_{k-1} / r_{k-2}
    float a1 = (t == 0) ? dsk[0] : BIGF;  // r_0 = BIG except r_0[0] = D[0,0]
    float b1 = BIGF, a2 = BIGF, b2 = BIGF;

    // preload diagonal k=1
    float dc0 = (i0 <= 1) ? dsk[DSK_STRIDE + i0] : BIGF;
    float dc1 = (i1 <= 1) ? dsk[DSK_STRIDE + i1] : BIGF;
    __syncthreads();

    const float* row = dsk + 2 * DSK_STRIDE;  // row for k=2 (prefetch target)
    int s0 = 1, s1 = 0, s2 = 2;               // ring slots: write k, read k-1, read k-2

    for (int k = 1; k <= KK - 1; ++k) {
        // prefetch diagonal k+1 (predicated; invalid lattice cells are BIG)
        float dn0 = BIGF, dn1 = BIGF;
        const int kn = k + 1;
        if (kn <= KK - 1) {
            if (i0 <= kn && kn - i0 <= NN - 1) dn0 = row[i0];
            if (i1 <= kn && kn - i1 <= NN - 1) dn1 = row[i1];
        }
        row += DSK_STRIDE;

        // neighbor (i0-1) values from r_{k-1}, r_{k-2}: shuffle in-warp, smem across warps
        float sh1 = __shfl_up_sync(0xffffffffu, b1, 1);
        float sh2 = __shfl_up_sync(0xffffffffu, b2, 1);
        float nb1, nb2;
        if (lane == 0) {
            nb1 = (w == 0) ? BIGF : wb[s1][w - 1];
            nb2 = (w == 0) ? BIGF : wb[s2][w - 1];
        } else { nb1 = sh1; nb2 = sh2; }

        // r_k[i] = D_k[i] + softmin(r_{k-2}[i-1], r_{k-1}[i-1], r_{k-1}[i])
        float n0 = dc0 + softmin3(nb2, nb1, a1);
        float n1 = dc1 + softmin3(a2, a1, b1);

        a2 = a1; b2 = b1; a1 = n0; b1 = n1;
        if (lane == 31) wb[s0][w] = b1;
        __syncthreads();

        int tmp = s2; s2 = s1; s1 = s0; s0 = tmp;
        dc0 = dn0; dc1 = dn1;
    }
    if (t == 1023) g_sdtw[z] = b1;   // r_{K-1}[N-1]
}

// ---------------- combine ----------------
__global__ void finalize_kernel(float* out) {
    float pos = g_sdtw[0] - 0.5f * (g_sdtw[1] + g_sdtw[2]);
    float idm = (float)(g_idm[0] + g_idm[1]);
    out[0] = (pos + idm) / 2048.0f;    // ALPHA = 1, NUM_FRAMES = 2048
}

// ---------------- launch ----------------
extern "C" void kernel_launch(void* const* d_in, const int* in_sizes, int n_in,
                              void* d_out, int out_size) {
    const float* a = (const float*)d_in[0];   // a_emb [1,2048,128] fp32
    const float* b = (const float*)d_in[1];   // b_emb [1,2048,128] fp32
    (void)in_sizes; (void)n_in; (void)out_size;

    norms_kernel<<<512, 256>>>(a, b);         // 4096 warps: norms + idm accumulator init
    dim3 g(32, 32, 3);
    pairdist_kernel<<<g, 256>>>(a, b);        // D in diagonal layout + fused idm
    softdtw_kernel<<<3, 1024>>>();            // 3 independent wavefronts
    finalize_kernel<<<1, 1>>>((float*)d_out);
}

// round 5
// speedup vs baseline: 1.2419x; 1.2419x over previous
#include <cuda_runtime.h>
#include <cuda_bf16.h>
#include <cstdint>

#define NN 2048
#define KK 4095              // number of anti-diagonals = 2N-1
#define BIGF 1e10f
#define DSK_STRIDE ((size_t)NN)
#define DSK_MAT ((size_t)KK * (size_t)NN)   // 8,386,560 floats per matrix

// ---------------- device scratch (no allocations allowed) ----------------
__device__ float  g_dsk[3 * KK * NN];   // ~100.6 MB, diagonal-major D for xy/xx/yy (fits L2)
__device__ float  g_norms[2 * NN];      // row norms of a (first 2048) and b (next 2048)
__device__ double g_idm[2];             // idm_a, idm_b accumulators
__device__ float  g_sdtw[3];            // softdtw(xy), softdtw(xx), softdtw(yy)

// ---------------- fast math helpers ----------------
__device__ __forceinline__ float ex2f(float x) {
    float y; asm("ex2.approx.ftz.f32 %0, %1;" : "=f"(y) : "f"(x)); return y;
}
__device__ __forceinline__ float lg2f_(float x) {
    float y; asm("lg2.approx.f32 %0, %1;" : "=f"(y) : "f"(x)); return y;
}

// softmin_gamma(v0,v1,v2) with gamma=0.1:
//   m - gamma*log( exp((m-v0)/g) + exp((m-v1)/g) + exp((m-v2)/g) )
// The min term's exp is exactly 1, so only 2 ex2 + 1 lg2 are needed.
#define C_EXP 14.4269504088896340f   /* 10 * log2(e)  (1/gamma = 10) */
#define C_LOG 0.0693147180559945f    /* 0.1 * ln(2) */
__device__ __forceinline__ float softmin3(float v0, float v1, float v2) {
    float m = fminf(fminf(v0, v1), v2);
    float p = (v0 == m) ? v1 : v0;
    float q = (v0 == m || v1 == m) ? v2 : v1;
    float e1 = ex2f((m - p) * C_EXP);
    float e2 = ex2f((m - q) * C_EXP);
    float s  = 1.0f + e1 + e2;
    return m - C_LOG * lg2f_(s);
}

__device__ __forceinline__ uint32_t smem_u32(const void* p) {
    uint32_t a;
    asm("{ .reg .u64 t; cvta.to.shared.u64 t, %1; cvt.u32.u64 %0, t; }" : "=r"(a) : "l"(p));
    return a;
}

// ---------------- row norms + accumulator init ----------------
__global__ void norms_kernel(const float* __restrict__ a, const float* __restrict__ b) {
    if (blockIdx.x == 0 && threadIdx.x == 0) { g_idm[0] = 0.0; g_idm[1] = 0.0; }
    int w    = blockIdx.x * (blockDim.x >> 5) + (threadIdx.x >> 5);
    int lane = threadIdx.x & 31;
    if (w >= 2 * NN) return;
    const float* src = (w < NN) ? (a + (size_t)w * 128) : (b + (size_t)(w - NN) * 128);
    float s = 0.0f;
#pragma unroll
    for (int q = 0; q < 4; q++) { float v = src[lane + 32 * q]; s = fmaf(v, v, s); }
#pragma unroll
    for (int off = 16; off; off >>= 1) s += __shfl_xor_sync(0xffffffffu, s, off);
    if (lane == 0) g_norms[w] = s;
}

// ---------------- pairwise sqdist GEMM: writes diagonal-major D, fuses idm ----------------
__global__ void __launch_bounds__(256) pairdist_kernel(const float* __restrict__ a,
                                                       const float* __restrict__ b) {
    __shared__ float pool[2 * 64 * 65];   // 33,280 B
    float* xsT = pool;                    // [kk][ii], stride 65 (conflict-free)
    float* ysT = pool + 64 * 65;

    const int z = blockIdx.z;             // 0: (a,b)  1: (a,a)  2: (b,b)
    const float* X  = (z == 2) ? b : a;
    const float* Y  = (z == 0) ? b : ((z == 1) ? a : b);
    const float* xn = g_norms + ((z == 2) ? NN : 0);
    const float* yn = g_norms + ((z == 1) ? 0 : NN);

    const int i0 = blockIdx.y * 64, j0 = blockIdx.x * 64;
    const int tid = threadIdx.x;
    const int tx = tid & 15, ty = tid >> 4;

    float acc[4][4];
#pragma unroll
    for (int r = 0; r < 4; r++)
#pragma unroll
        for (int c = 0; c < 4; c++) acc[r][c] = 0.0f;

    for (int kc = 0; kc < 128; kc += 64) {
        const int kk = tid & 63, ib = tid >> 6;
#pragma unroll
        for (int ii = ib; ii < 64; ii += 4) {
            xsT[kk * 65 + ii] = X[(size_t)(i0 + ii) * 128 + kc + kk];
            ysT[kk * 65 + ii] = Y[(size_t)(j0 + ii) * 128 + kc + kk];
        }
        __syncthreads();
#pragma unroll 4
        for (int k2 = 0; k2 < 64; ++k2) {
            float ra[4], rb[4];
#pragma unroll
            for (int r = 0; r < 4; r++) ra[r] = xsT[k2 * 65 + ty * 4 + r];
#pragma unroll
            for (int c = 0; c < 4; c++) rb[c] = ysT[k2 * 65 + tx * 4 + c];
#pragma unroll
            for (int r = 0; r < 4; r++)
#pragma unroll
                for (int c = 0; c < 4; c++) acc[r][c] = fmaf(ra[r], rb[c], acc[r][c]);
        }
        __syncthreads();
    }

    float xnv[4], ynv[4];
#pragma unroll
    for (int r = 0; r < 4; r++) xnv[r] = xn[i0 + ty * 4 + r];
#pragma unroll
    for (int c = 0; c < 4; c++) ynv[c] = yn[j0 + tx * 4 + c];

    float* ds = pool;                     // reuse; 64 x 66 floats
    float lsum = 0.0f;
    const float inv_n = 1.0f / 2048.0f;
    const float thr   = 10.0f / 2048.0f;  // SIGMA / seq_len (exact in fp32)
#pragma unroll
    for (int r = 0; r < 4; r++) {
#pragma unroll
        for (int c = 0; c < 4; c++) {
            float d = fmaxf(xnv[r] + ynv[c] - 2.0f * acc[r][c], 0.0f);
            ds[(ty * 4 + r) * 66 + tx * 4 + c] = d;
            if (z) {
                int ig = i0 + ty * 4 + r, jg = j0 + tx * 4 + c;
                float gd   = (float)(ig - jg) * inv_n;
                float wgt  = fmaf(gd, gd, 1.0f);
                float diff = fabsf(gd) - thr;
                float prob = fmaxf(2.0f - d, 0.0f);
                lsum += (diff > 0.0f) ? (wgt * prob) : d;
            }
        }
    }
    if (z) {
#pragma unroll
        for (int off = 16; off; off >>= 1) lsum += __shfl_xor_sync(0xffffffffu, lsum, off);
        if ((tid & 31) == 0) atomicAdd(&g_idm[z - 1], (double)lsum);
    }
    __syncthreads();  // ds fully written before diag write-out

    float* dst = g_dsk + (size_t)z * DSK_MAT + (size_t)(i0 + j0) * DSK_STRIDE + i0;
    const int w = tid >> 5, lane = tid & 31;
    for (int d = w; d < 127; d += 8) {
        int lo = max(0, d - 63), hi = min(63, d);
        for (int e = lo + lane; e <= hi; e += 32) {
            dst[(size_t)d * DSK_STRIDE + e] = ds[e * 66 + (d - e)];
        }
    }
}

// ---------------- softDTW wavefront: 8-CTA cluster per matrix ----------------
// 256 threads/CTA, 1 element/thread. Cross-CTA boundary handoff: packed
// (tag<<32 | floatbits) u64 into right neighbor's per-k inbox slot via DSMEM.
__global__ void __launch_bounds__(256, 1) __cluster_dims__(8, 1, 1)
softdtw_kernel() {
    const int bz   = blockIdx.x;
    const int z    = bz >> 3;            // matrix id
    const int rank = bz & 7;             // position within cluster (wavefront segment)
    const float* __restrict__ dsk = g_dsk + (size_t)z * DSK_MAT;
    const int t = threadIdx.x;
    const int lane = t & 31, w = t >> 5;
    const int i = rank * 256 + t;        // global element index on each diagonal

    __shared__ unsigned long long inbox[4096];  // slot k: left neighbor's diag-k boundary, tag=k+1
    __shared__ float wb[3][8];                  // warp-boundary ring (lane31 values)

    for (int s = t; s < 4096; s += 256) inbox[s] = 0ULL;
    if (t < 8) { wb[0][t] = BIGF; wb[2][t] = BIGF; }
    __syncthreads();
    asm volatile("barrier.cluster.arrive.aligned;" ::: "memory");
    asm volatile("barrier.cluster.wait.aligned;" ::: "memory");

    const uint32_t inbox_addr = smem_u32(inbox);
    uint32_t rem_inbox = 0;
    if (rank < 7) {
        asm("mapa.shared::cluster.u32 %0, %1, %2;"
            : "=r"(rem_inbox) : "r"(inbox_addr), "r"(rank + 1));
    }
    // pre-publish diag-0 boundary (always BIG: boundary element is never i==0)
    if (t == 255 && rank < 7) {
        unsigned long long p = (1ULL << 32) | (unsigned long long)__float_as_uint(BIGF);
        asm volatile("st.shared::cluster.u64 [%0], %1;" :: "r"(rem_inbox), "l"(p) : "memory");
    }

    // register rows: r1 = r_{k-1}[i], r2 = r_{k-2}[i]
    float r1 = (i == 0) ? dsk[0] : BIGF;   // r_0
    float r2 = BIGF;                       // r_{-1}
    float prev_in = BIGF;                  // left-CTA boundary of diag k-2

    // D prefetch ring, depth 4 (D lives in L2, ~250 cyc)
    float dd0 = (i <= 1) ? dsk[1 * NN + i] : BIGF;
    float dd1 = (i <= 2) ? dsk[2 * NN + i] : BIGF;
    float dd2 = (i <= 3) ? dsk[3 * NN + i] : BIGF;
    float dd3 = (i <= 4) ? dsk[4 * NN + i] : BIGF;
    const float* row = dsk + (size_t)5 * NN + i;   // element address for diag k+4 at k=1

    int s0 = 1, s1 = 0, s2 = 2;
    for (int k = 1; k <= KK - 1; ++k) {
        // prefetch diag k+4
        const int kn = k + 4;
        float dn = BIGF;
        if (kn <= KK - 1 && i <= kn && kn - i <= NN - 1) dn = *row;
        row += NN;

        // neighbor (i-1) values from r_{k-1}, r_{k-2}
        float sh1 = __shfl_up_sync(0xffffffffu, r1, 1);
        float sh2 = __shfl_up_sync(0xffffffffu, r2, 1);
        float nb1, nb2;
        if (lane == 0) {
            if (w == 0) {
                if (rank == 0) { nb1 = BIGF; nb2 = BIGF; }
                else {
                    unsigned long long v;
                    const uint32_t addr = inbox_addr + (uint32_t)((k - 1) * 8);
                    do {
                        asm volatile("ld.volatile.shared.u64 %0, [%1];" : "=l"(v) : "r"(addr));
                    } while ((unsigned)(v >> 32) != (unsigned)k);
                    nb1 = __uint_as_float((unsigned)v);
                    nb2 = prev_in;
                    prev_in = nb1;
                }
            } else {
                nb1 = wb[s1][w - 1];
                nb2 = wb[s2][w - 1];
            }
        } else { nb1 = sh1; nb2 = sh2; }

        // r_k[i] = D_k[i] + softmin(r_{k-2}[i-1], r_{k-1}[i-1], r_{k-1}[i])
        float nv = dd0 + softmin3(nb2, nb1, r1);
        r2 = r1; r1 = nv;

        if (lane == 31) {
            wb[s0][w] = r1;
            if (t == 255 && rank < 7) {
                unsigned long long p = (((unsigned long long)(k + 1)) << 32)
                                     | (unsigned long long)__float_as_uint(r1);
                asm volatile("st.shared::cluster.u64 [%0], %1;"
                             :: "r"(rem_inbox + (uint32_t)(k * 8)), "l"(p) : "memory");
            }
        }
        __syncthreads();
        int tmp = s2; s2 = s1; s1 = s0; s0 = tmp;
        dd0 = dd1; dd1 = dd2; dd2 = dd3; dd3 = dn;
    }
    if (rank == 7 && t == 255) g_sdtw[z] = r1;   // r_{K-1}[N-1]

    asm volatile("barrier.cluster.arrive.aligned;" ::: "memory");
    asm volatile("barrier.cluster.wait.aligned;" ::: "memory");
}

// ---------------- combine ----------------
__global__ void finalize_kernel(float* out) {
    float pos = g_sdtw[0] - 0.5f * (g_sdtw[1] + g_sdtw[2]);
    float idm = (float)(g_idm[0] + g_idm[1]);
    out[0] = (pos + idm) / 2048.0f;    // ALPHA = 1, NUM_FRAMES = 2048
}

// ---------------- launch ----------------
extern "C" void kernel_launch(void* const* d_in, const int* in_sizes, int n_in,
                              void* d_out, int out_size) {
    const float* a = (const float*)d_in[0];   // a_emb [1,2048,128] fp32
    const float* b = (const float*)d_in[1];   // b_emb [1,2048,128] fp32
    (void)in_sizes; (void)n_in; (void)out_size;

    norms_kernel<<<512, 256>>>(a, b);
    dim3 g(32, 32, 3);
    pairdist_kernel<<<g, 256>>>(a, b);        // D in diagonal layout + fused idm
    softdtw_kernel<<<24, 256>>>();            // 3 clusters x 8 CTAs, pipelined wavefronts
    finalize_kernel<<<1, 1>>>((float*)d_out);
}

// round 6
// speedup vs baseline: 1.2748x; 1.0265x over previous
#include <cuda_runtime.h>
#include <cuda_bf16.h>
#include <cstdint>

#define NN 2048
#define KK 4095              // number of anti-diagonals = 2N-1
#define BIGF 1e10f
#define DSK_STRIDE ((size_t)NN)
#define DSK_MAT ((size_t)KK * (size_t)NN)   // 8,386,560 floats per matrix

// ---------------- device scratch (no allocations allowed) ----------------
__device__ float  g_dsk[3 * KK * NN];   // ~100.6 MB, diagonal-major D for xy/xx/yy
__device__ float  g_norms[2 * NN];      // row norms of a (first 2048) and b (next 2048)
__device__ double g_idm[2];             // idm_a, idm_b accumulators
__device__ float  g_sdtw[3];            // softdtw(xy), softdtw(xx), softdtw(yy)

// ---------------- fast math helpers ----------------
__device__ __forceinline__ float ex2f(float x) {
    float y; asm("ex2.approx.ftz.f32 %0, %1;" : "=f"(y) : "f"(x)); return y;
}
__device__ __forceinline__ float lg2f_(float x) {
    float y; asm("lg2.approx.f32 %0, %1;" : "=f"(y) : "f"(x)); return y;
}

#define C_EXP 14.4269504088896340f   /* 10 * log2(e)  (1/gamma = 10) */
#define C_LOG 0.0693147180559945f    /* 0.1 * ln(2) */

__device__ __forceinline__ uint32_t smem_u32(const void* p) {
    uint32_t a;
    asm("{ .reg .u64 t; cvta.to.shared.u64 t, %1; cvt.u32.u64 %0, t; }" : "=r"(a) : "l"(p));
    return a;
}

// ---------------- row norms + accumulator init ----------------
__global__ void norms_kernel(const float* __restrict__ a, const float* __restrict__ b) {
    if (blockIdx.x == 0 && threadIdx.x == 0) { g_idm[0] = 0.0; g_idm[1] = 0.0; }
    int w    = blockIdx.x * (blockDim.x >> 5) + (threadIdx.x >> 5);
    int lane = threadIdx.x & 31;
    if (w >= 2 * NN) return;
    const float* src = (w < NN) ? (a + (size_t)w * 128) : (b + (size_t)(w - NN) * 128);
    float s = 0.0f;
#pragma unroll
    for (int q = 0; q < 4; q++) { float v = src[lane + 32 * q]; s = fmaf(v, v, s); }
#pragma unroll
    for (int off = 16; off; off >>= 1) s += __shfl_xor_sync(0xffffffffu, s, off);
    if (lane == 0) g_norms[w] = s;
}

// ---------------- pairwise sqdist GEMM: writes diagonal-major D, fuses idm ----------------
__global__ void __launch_bounds__(256) pairdist_kernel(const float* __restrict__ a,
                                                       const float* __restrict__ b) {
    __shared__ float pool[2 * 64 * 65];   // 33,280 B
    float* xsT = pool;                    // [kk][ii], stride 65 (conflict-free)
    float* ysT = pool + 64 * 65;

    const int z = blockIdx.z;             // 0: (a,b)  1: (a,a)  2: (b,b)
    const float* X  = (z == 2) ? b : a;
    const float* Y  = (z == 0) ? b : ((z == 1) ? a : b);
    const float* xn = g_norms + ((z == 2) ? NN : 0);
    const float* yn = g_norms + ((z == 1) ? 0 : NN);

    const int i0 = blockIdx.y * 64, j0 = blockIdx.x * 64;
    const int tid = threadIdx.x;
    const int tx = tid & 15, ty = tid >> 4;

    float acc[4][4];
#pragma unroll
    for (int r = 0; r < 4; r++)
#pragma unroll
        for (int c = 0; c < 4; c++) acc[r][c] = 0.0f;

    for (int kc = 0; kc < 128; kc += 64) {
        const int kk = tid & 63, ib = tid >> 6;
#pragma unroll
        for (int ii = ib; ii < 64; ii += 4) {
            xsT[kk * 65 + ii] = X[(size_t)(i0 + ii) * 128 + kc + kk];
            ysT[kk * 65 + ii] = Y[(size_t)(j0 + ii) * 128 + kc + kk];
        }
        __syncthreads();
#pragma unroll 4
        for (int k2 = 0; k2 < 64; ++k2) {
            float ra[4], rb[4];
#pragma unroll
            for (int r = 0; r < 4; r++) ra[r] = xsT[k2 * 65 + ty * 4 + r];
#pragma unroll
            for (int c = 0; c < 4; c++) rb[c] = ysT[k2 * 65 + tx * 4 + c];
#pragma unroll
            for (int r = 0; r < 4; r++)
#pragma unroll
                for (int c = 0; c < 4; c++) acc[r][c] = fmaf(ra[r], rb[c], acc[r][c]);
        }
        __syncthreads();
    }

    float xnv[4], ynv[4];
#pragma unroll
    for (int r = 0; r < 4; r++) xnv[r] = xn[i0 + ty * 4 + r];
#pragma unroll
    for (int c = 0; c < 4; c++) ynv[c] = yn[j0 + tx * 4 + c];

    float* ds = pool;                     // reuse; 64 x 66 floats
    float lsum = 0.0f;
    const float inv_n = 1.0f / 2048.0f;
    const float thr   = 10.0f / 2048.0f;  // SIGMA / seq_len (exact in fp32)
#pragma unroll
    for (int r = 0; r < 4; r++) {
#pragma unroll
        for (int c = 0; c < 4; c++) {
            float d = fmaxf(xnv[r] + ynv[c] - 2.0f * acc[r][c], 0.0f);
            ds[(ty * 4 + r) * 66 + tx * 4 + c] = d;
            if (z) {
                int ig = i0 + ty * 4 + r, jg = j0 + tx * 4 + c;
                float gd   = (float)(ig - jg) * inv_n;
                float wgt  = fmaf(gd, gd, 1.0f);
                float diff = fabsf(gd) - thr;
                float prob = fmaxf(2.0f - d, 0.0f);
                lsum += (diff > 0.0f) ? (wgt * prob) : d;
            }
        }
    }
    if (z) {
#pragma unroll
        for (int off = 16; off; off >>= 1) lsum += __shfl_xor_sync(0xffffffffu, lsum, off);
        if ((tid & 31) == 0) atomicAdd(&g_idm[z - 1], (double)lsum);
    }
    __syncthreads();  // ds fully written before diag write-out

    float* dst = g_dsk + (size_t)z * DSK_MAT + (size_t)(i0 + j0) * DSK_STRIDE + i0;
    const int w = tid >> 5, lane = tid & 31;
    for (int d = w; d < 127; d += 8) {
        int lo = max(0, d - 63), hi = min(63, d);
        for (int e = lo + lane; e <= hi; e += 32) {
            dst[(size_t)d * DSK_STRIDE + e] = ds[e * 66 + (d - e)];
        }
    }
}

// ---------------- softDTW: barrier-free self-synchronizing wavefront ----------------
// 3 clusters x 8 CTAs x 256 threads, 1 element/thread. No __syncthreads in the loop.
// Warp->warp handoff: tagged u64 smem ring (256 slots). CTA->CTA: full-depth DSMEM inbox.
#define PF 8
__global__ void __launch_bounds__(256, 1) __cluster_dims__(8, 1, 1)
softdtw_kernel() {
    const int bz   = blockIdx.x;
    const int z    = bz >> 3;            // matrix id
    const int rank = bz & 7;             // segment within cluster
    const float* __restrict__ dsk = g_dsk + (size_t)z * DSK_MAT;
    const int t = threadIdx.x;
    const int lane = t & 31, w = t >> 5;
    const int i = rank * 256 + t;        // global element index on each diagonal

    __shared__ unsigned long long inbox[4096];     // 32 KB, slot k: left CTA's r_{k-1}, tag=k
    __shared__ unsigned long long ring[7][256];    // 14 KB, boundary w -> w+1
    __shared__ unsigned int prog[8];               // consumer progress (for backpressure)

    for (int s = t; s < 4096; s += 256) inbox[s] = 0ULL;
    for (int s = t; s < 7 * 256; s += 256) ((unsigned long long*)ring)[s] = 0ULL;
    if (t < 8) prog[t] = 0u;
    __syncthreads();
    if (t == 0) {   // pre-publish diag-0 boundaries (r_0 at any boundary is BIG)
        unsigned long long p0 = (1ULL << 32) | (unsigned long long)__float_as_uint(BIGF);
        for (int b = 0; b < 7; b++) ring[b][1] = p0;
    }
    __syncthreads();
    asm volatile("barrier.cluster.arrive.aligned;" ::: "memory");
    asm volatile("barrier.cluster.wait.aligned;" ::: "memory");

    const uint32_t inbox_a = smem_u32(inbox);
    const uint32_t ring_a  = smem_u32(ring);
    const uint32_t prog_a  = smem_u32(prog);
    uint32_t rem_inbox = 0;
    if (rank < 7) {
        asm("mapa.shared::cluster.u32 %0, %1, %2;"
            : "=r"(rem_inbox) : "r"(inbox_a), "r"(rank + 1));
    }
    // cross-CTA pre-publish of diag-0 boundary into right neighbor's inbox[1]
    if (t == 255 && rank < 7) {
        unsigned long long p0 = (1ULL << 32) | (unsigned long long)__float_as_uint(BIGF);
        asm volatile("st.shared::cluster.u64 [%0], %1;" :: "r"(rem_inbox + 8u), "l"(p0) : "memory");
    }

    const bool has_left  = (w > 0) || (rank > 0);
    const bool pub_ring  = (w < 7);
    const bool pub_dsmem = (w == 7) && (rank < 7);
    const uint32_t cons_base = (w == 0) ? inbox_a : (ring_a + (uint32_t)(w - 1) * 2048u);
    const uint32_t cons_mask = (w == 0) ? 0xFFFFFFFFu : 2047u;   // byte-offset mask
    const uint32_t prod_base = ring_a + (uint32_t)w * 2048u;     // valid when w<7
    const uint32_t myprog_a  = prog_a + 4u * (uint32_t)w;        // this warp's consumer progress
    const uint32_t rprog_a   = prog_a + 4u * (uint32_t)(w + 1);  // right-neighbor progress

    // state: r1 = r_{k-1}[i]; shp = r_{k-2}[i-1] (prev shfl); prev_in = boundary r_{k-2}[i-1]
    float r1 = (i == 0) ? dsk[0] : BIGF;
    float shp = BIGF, prev_in = BIGF;

    // D prefetch ring, depth PF
    float dd[PF];
#pragma unroll
    for (int q = 0; q < PF; q++) {
        int kn = 1 + q;
        dd[q] = (kn <= KK - 1 && kn >= i && kn <= i + (NN - 1))
              ? dsk[(size_t)kn * NN + i] : BIGF;
    }
    const float* __restrict__ prow = dsk + (size_t)(1 + PF) * NN + i;

    for (int k = 1; k <= KK - 1; ++k) {
        // prefetch diag k+PF (per-lane predicated, coalesced)
        const int kn = k + PF;
        float dn = BIGF;
        if (kn <= KK - 1) {
            if (kn >= i && kn <= i + (NN - 1)) dn = *prow;
        }
        prow += NN;

        // poll left boundary r_{k-1} (warp-uniform: all lanes read the same slot)
        float in1 = BIGF;
        if (has_left) {
            unsigned long long v;
            const uint32_t addr = cons_base + (((uint32_t)k * 8u) & cons_mask);
            do {
                asm volatile("ld.volatile.shared.u64 %0, [%1];" : "=l"(v) : "r"(addr));
            } while ((unsigned)(v >> 32) != (unsigned)k);
            in1 = __uint_as_float((unsigned)v);
        }

        float sh  = __shfl_up_sync(0xffffffffu, r1, 1);
        float nb1 = (lane == 0) ? in1 : sh;        // r_{k-1}[i-1]
        float nb2 = (lane == 0) ? prev_in : shp;   // r_{k-2}[i-1]

        // softmin over (nb2, nb1, r1): 3 parallel ex2 off the min pivot
        float m  = fminf(fminf(nb2, nb1), r1);
        float e0 = ex2f((m - nb2) * C_EXP);
        float e1 = ex2f((m - nb1) * C_EXP);
        float e2 = ex2f((m - r1)  * C_EXP);
        float s  = (e0 + e1) + e2;
        float nv = dd[0] + fmaf(-C_LOG, lg2f_(s), m);

        shp = sh; prev_in = in1; r1 = nv;

        // publish r_k boundary for the right consumer (tag k+1)
        {
            unsigned long long p = (((unsigned long long)(k + 1)) << 32)
                                 | (unsigned long long)__float_as_uint(r1);
            if (lane == 31) {
                if (pub_ring) {
                    const uint32_t pa = prod_base + (((uint32_t)(k + 1) * 8u) & 2047u);
                    asm volatile("st.volatile.shared.u64 [%0], %1;" :: "r"(pa), "l"(p) : "memory");
                } else if (pub_dsmem) {
                    asm volatile("st.shared::cluster.u64 [%0], %1;"
                                 :: "r"(rem_inbox + (uint32_t)(k + 1) * 8u), "l"(p) : "memory");
                }
            }
        }

        // progress + ring backpressure, every 64 diagonals
        if ((k & 63) == 0) {
            if (w > 0 && lane == 0) {
                asm volatile("st.volatile.shared.u32 [%0], %1;" :: "r"(myprog_a), "r"((unsigned)k) : "memory");
            }
            if (pub_ring) {
                unsigned pr;
                do {
                    asm volatile("ld.volatile.shared.u32 %0, [%1];" : "=r"(pr) : "r"(rprog_a));
                } while ((unsigned)k - pr > 160u);
            }
        }

        // rotate prefetch ring (register renaming under unroll)
#pragma unroll
        for (int q = 0; q < PF - 1; q++) dd[q] = dd[q + 1];
        dd[PF - 1] = dn;
    }

    if (rank == 7 && t == 255) g_sdtw[z] = r1;   // r_{K-1}[N-1]

    asm volatile("barrier.cluster.arrive.aligned;" ::: "memory");
    asm volatile("barrier.cluster.wait.aligned;" ::: "memory");
}

// ---------------- combine ----------------
__global__ void finalize_kernel(float* out) {
    float pos = g_sdtw[0] - 0.5f * (g_sdtw[1] + g_sdtw[2]);
    float idm = (float)(g_idm[0] + g_idm[1]);
    out[0] = (pos + idm) / 2048.0f;    // ALPHA = 1, NUM_FRAMES = 2048
}

// ---------------- launch ----------------
extern "C" void kernel_launch(void* const* d_in, const int* in_sizes, int n_in,
                              void* d_out, int out_size) {
    const float* a = (const float*)d_in[0];   // a_emb [1,2048,128] fp32
    const float* b = (const float*)d_in[1];   // b_emb [1,2048,128] fp32
    (void)in_sizes; (void)n_in; (void)out_size;

    norms_kernel<<<512, 256>>>(a, b);
    dim3 g(32, 32, 3);
    pairdist_kernel<<<g, 256>>>(a, b);        // D in diagonal layout + fused idm
    softdtw_kernel<<<24, 256>>>();            // 3 clusters x 8 CTAs, barrier-free wavefronts
    finalize_kernel<<<1, 1>>>((float*)d_out);
}

// round 7
// speedup vs baseline: 1.5375x; 1.2060x over previous
#include <cuda_runtime.h>
#include <cuda_bf16.h>
#include <cstdint>

#define NN 2048
#define KK 4095              // number of anti-diagonals = 2N-1
#define BIGF 1e10f
#define DSK_STRIDE ((size_t)NN)
#define DSK_MAT ((size_t)KK * (size_t)NN)   // 8,386,560 floats per matrix

// ---------------- device scratch (no allocations allowed) ----------------
__device__ float  g_dsk[3 * KK * NN];   // ~100.6 MB, diagonal-major D for xy/xx/yy
__device__ float  g_norms[2 * NN];      // row norms of a (first 2048) and b (next 2048)
__device__ double g_idm[2];             // idm_a, idm_b accumulators
__device__ float  g_sdtw[3];            // softdtw(xy), softdtw(xx), softdtw(yy)

// ---------------- fast math helpers ----------------
__device__ __forceinline__ float ex2f(float x) {
    float y; asm("ex2.approx.ftz.f32 %0, %1;" : "=f"(y) : "f"(x)); return y;
}
__device__ __forceinline__ float lg2f_(float x) {
    float y; asm("lg2.approx.f32 %0, %1;" : "=f"(y) : "f"(x)); return y;
}

#define C_EXP 14.4269504088896340f   /* 10 * log2(e)  (1/gamma = 10) */
#define C_LOG 0.0693147180559945f    /* 0.1 * ln(2) */

__device__ __forceinline__ uint32_t smem_u32(const void* p) {
    uint32_t a;
    asm("{ .reg .u64 t; cvta.to.shared.u64 t, %1; cvt.u32.u64 %0, t; }" : "=r"(a) : "l"(p));
    return a;
}

// ---------------- row norms + accumulator init ----------------
__global__ void norms_kernel(const float* __restrict__ a, const float* __restrict__ b) {
    if (blockIdx.x == 0 && threadIdx.x == 0) { g_idm[0] = 0.0; g_idm[1] = 0.0; }
    int w    = blockIdx.x * (blockDim.x >> 5) + (threadIdx.x >> 5);
    int lane = threadIdx.x & 31;
    if (w >= 2 * NN) return;
    const float* src = (w < NN) ? (a + (size_t)w * 128) : (b + (size_t)(w - NN) * 128);
    float s = 0.0f;
#pragma unroll
    for (int q = 0; q < 4; q++) { float v = src[lane + 32 * q]; s = fmaf(v, v, s); }
#pragma unroll
    for (int off = 16; off; off >>= 1) s += __shfl_xor_sync(0xffffffffu, s, off);
    if (lane == 0) g_norms[w] = s;
}

// ---------------- pairwise sqdist GEMM: writes diagonal-major D, fuses idm ----------------
__global__ void __launch_bounds__(256) pairdist_kernel(const float* __restrict__ a,
                                                       const float* __restrict__ b) {
    __shared__ float pool[2 * 64 * 65];   // 33,280 B
    float* xsT = pool;                    // [kk][ii], stride 65 (conflict-free)
    float* ysT = pool + 64 * 65;

    const int z = blockIdx.z;             // 0: (a,b)  1: (a,a)  2: (b,b)
    const float* X  = (z == 2) ? b : a;
    const float* Y  = (z == 0) ? b : ((z == 1) ? a : b);
    const float* xn = g_norms + ((z == 2) ? NN : 0);
    const float* yn = g_norms + ((z == 1) ? 0 : NN);

    const int i0 = blockIdx.y * 64, j0 = blockIdx.x * 64;
    const int tid = threadIdx.x;
    const int tx = tid & 15, ty = tid >> 4;

    float acc[4][4];
#pragma unroll
    for (int r = 0; r < 4; r++)
#pragma unroll
        for (int c = 0; c < 4; c++) acc[r][c] = 0.0f;

    for (int kc = 0; kc < 128; kc += 64) {
        const int kk = tid & 63, ib = tid >> 6;
#pragma unroll
        for (int ii = ib; ii < 64; ii += 4) {
            xsT[kk * 65 + ii] = X[(size_t)(i0 + ii) * 128 + kc + kk];
            ysT[kk * 65 + ii] = Y[(size_t)(j0 + ii) * 128 + kc + kk];
        }
        __syncthreads();
#pragma unroll 4
        for (int k2 = 0; k2 < 64; ++k2) {
            float ra[4], rb[4];
#pragma unroll
            for (int r = 0; r < 4; r++) ra[r] = xsT[k2 * 65 + ty * 4 + r];
#pragma unroll
            for (int c = 0; c < 4; c++) rb[c] = ysT[k2 * 65 + tx * 4 + c];
#pragma unroll
            for (int r = 0; r < 4; r++)
#pragma unroll
                for (int c = 0; c < 4; c++) acc[r][c] = fmaf(ra[r], rb[c], acc[r][c]);
        }
        __syncthreads();
    }

    float xnv[4], ynv[4];
#pragma unroll
    for (int r = 0; r < 4; r++) xnv[r] = xn[i0 + ty * 4 + r];
#pragma unroll
    for (int c = 0; c < 4; c++) ynv[c] = yn[j0 + tx * 4 + c];

    float* ds = pool;                     // reuse; 64 x 66 floats
    float lsum = 0.0f;
    const float inv_n = 1.0f / 2048.0f;
    const float thr   = 10.0f / 2048.0f;  // SIGMA / seq_len (exact in fp32)
#pragma unroll
    for (int r = 0; r < 4; r++) {
#pragma unroll
        for (int c = 0; c < 4; c++) {
            float d = fmaxf(xnv[r] + ynv[c] - 2.0f * acc[r][c], 0.0f);
            ds[(ty * 4 + r) * 66 + tx * 4 + c] = d;
            if (z) {
                int ig = i0 + ty * 4 + r, jg = j0 + tx * 4 + c;
                float gd   = (float)(ig - jg) * inv_n;
                float wgt  = fmaf(gd, gd, 1.0f);
                float diff = fabsf(gd) - thr;
                float prob = fmaxf(2.0f - d, 0.0f);
                lsum += (diff > 0.0f) ? (wgt * prob) : d;
            }
        }
    }
    if (z) {
#pragma unroll
        for (int off = 16; off; off >>= 1) lsum += __shfl_xor_sync(0xffffffffu, lsum, off);
        if ((tid & 31) == 0) atomicAdd(&g_idm[z - 1], (double)lsum);
    }
    __syncthreads();  // ds fully written before diag write-out

    float* dst = g_dsk + (size_t)z * DSK_MAT + (size_t)(i0 + j0) * DSK_STRIDE + i0;
    const int w = tid >> 5, lane = tid & 31;
    for (int d = w; d < 127; d += 8) {
        int lo = max(0, d - 63), hi = min(63, d);
        for (int e = lo + lane; e <= hi; e += 32) {
            dst[(size_t)d * DSK_STRIDE + e] = ds[e * 66 + (d - e)];
        }
    }
}

// ---------------- softDTW: barrier-free wavefront, 8x-unrolled for real prefetch depth ----------------
#define PF 8
__global__ void __launch_bounds__(256, 1) __cluster_dims__(8, 1, 1)
softdtw_kernel() {
    const int bz   = blockIdx.x;
    const int z    = bz >> 3;            // matrix id
    const int rank = bz & 7;             // segment within cluster
    const float* __restrict__ dsk = g_dsk + (size_t)z * DSK_MAT;
    const int t = threadIdx.x;
    const int lane = t & 31, w = t >> 5;
    const int i = rank * 256 + t;        // global element index on each diagonal

    __shared__ unsigned long long inbox[4096];     // 32 KB, slot k: left CTA's r_{k-1}, tag=k
    __shared__ unsigned long long ring[7][256];    // 14 KB, boundary w -> w+1
    __shared__ unsigned int prog[8];               // consumer progress (for backpressure)

    for (int s = t; s < 4096; s += 256) inbox[s] = 0ULL;
    for (int s = t; s < 7 * 256; s += 256) ((unsigned long long*)ring)[s] = 0ULL;
    if (t < 8) prog[t] = 0u;
    __syncthreads();
    if (t == 0) {   // pre-publish diag-0 boundaries (r_0 at any boundary is BIG)
        unsigned long long p0 = (1ULL << 32) | (unsigned long long)__float_as_uint(BIGF);
        for (int b = 0; b < 7; b++) ring[b][1] = p0;
    }
    __syncthreads();
    asm volatile("barrier.cluster.arrive.aligned;" ::: "memory");
    asm volatile("barrier.cluster.wait.aligned;" ::: "memory");

    const uint32_t inbox_a = smem_u32(inbox);
    const uint32_t ring_a  = smem_u32(ring);
    const uint32_t prog_a  = smem_u32(prog);
    uint32_t rem_inbox = 0;
    if (rank < 7) {
        asm("mapa.shared::cluster.u32 %0, %1, %2;"
            : "=r"(rem_inbox) : "r"(inbox_a), "r"(rank + 1));
    }
    if (t == 255 && rank < 7) {   // cross-CTA pre-publish of diag-0 boundary
        unsigned long long p0 = (1ULL << 32) | (unsigned long long)__float_as_uint(BIGF);
        asm volatile("st.shared::cluster.u64 [%0], %1;" :: "r"(rem_inbox + 8u), "l"(p0) : "memory");
    }

    const bool has_left  = (w > 0) || (rank > 0);
    const bool pub_ring  = (w < 7);
    const bool pub_dsmem = (w == 7) && (rank < 7);
    const uint32_t cons_base = (w == 0) ? inbox_a : (ring_a + (uint32_t)(w - 1) * 2048u);
    const uint32_t cons_mask = (w == 0) ? 0xFFFFFFFFu : 2047u;   // byte-offset mask
    const uint32_t prod_base = ring_a + (uint32_t)w * 2048u;     // valid when w<7
    const uint32_t myprog_a  = prog_a + 4u * (uint32_t)w;
    const uint32_t rprog_a   = prog_a + 4u * (uint32_t)(w + 1);

    // state: r1 = r_{k-1}[i]; shp = r_{k-2}[i-1] (prev shfl); prev_in = boundary r_{k-2}[i-1]
    float r1 = (i == 0) ? dsk[0] : BIGF;
    float shp = BIGF, prev_in = BIGF;

    // D prefetch ring, depth PF. With the main loop unrolled by PF, the rotation is
    // pure register renaming: a value loaded at iter j is first consumed at iter j+PF.
    float dd[PF];
#pragma unroll
    for (int q = 0; q < PF; q++) {
        int kn = 1 + q;
        dd[q] = (kn <= KK - 1 && kn >= i && kn <= i + (NN - 1))
              ? dsk[(size_t)kn * NN + i] : BIGF;
    }
    const float* __restrict__ prow = dsk + (size_t)(1 + PF) * NN + i;

    auto body = [&](int k) {
        // prefetch diag k+PF
        const int kn = k + PF;
        float dn = BIGF;
        if (kn <= KK - 1) {
            if (kn >= i && kn <= i + (NN - 1)) dn = *prow;
        }
        prow += NN;

        // poll left boundary r_{k-1} (warp-uniform broadcast LDS)
        float in1 = BIGF;
        if (has_left) {
            unsigned long long v;
            const uint32_t addr = cons_base + (((uint32_t)k * 8u) & cons_mask);
            do {
                asm volatile("ld.volatile.shared.u64 %0, [%1];" : "=l"(v) : "r"(addr));
            } while ((unsigned)(v >> 32) != (unsigned)k);
            in1 = __uint_as_float((unsigned)v);
        }

        float sh  = __shfl_up_sync(0xffffffffu, r1, 1);
        float nb1 = (lane == 0) ? in1 : sh;        // r_{k-1}[i-1]
        float nb2 = (lane == 0) ? prev_in : shp;   // r_{k-2}[i-1]

        // softmin over (nb2, nb1, r1): 3 parallel ex2 off the min pivot
        float m  = fminf(fminf(nb2, nb1), r1);
        float e0 = ex2f((m - nb2) * C_EXP);
        float e1 = ex2f((m - nb1) * C_EXP);
        float e2 = ex2f((m - r1)  * C_EXP);
        float s  = (e0 + e1) + e2;
        float nv = dd[0] + fmaf(-C_LOG, lg2f_(s), m);

        shp = sh; prev_in = in1; r1 = nv;

        // publish r_k boundary (tag k+1)
        if (lane == 31) {
            unsigned long long p = (((unsigned long long)(k + 1)) << 32)
                                 | (unsigned long long)__float_as_uint(r1);
            if (pub_ring) {
                const uint32_t pa = prod_base + (((uint32_t)(k + 1) * 8u) & 2047u);
                asm volatile("st.volatile.shared.u64 [%0], %1;" :: "r"(pa), "l"(p) : "memory");
            } else if (pub_dsmem) {
                asm volatile("st.shared::cluster.u64 [%0], %1;"
                             :: "r"(rem_inbox + (uint32_t)(k + 1) * 8u), "l"(p) : "memory");
            }
        }

        // progress + ring backpressure, every 64 diagonals
        if ((k & 63) == 0) {
            if (w > 0 && lane == 0) {
                asm volatile("st.volatile.shared.u32 [%0], %1;" :: "r"(myprog_a), "r"((unsigned)k) : "memory");
            }
            if (pub_ring) {
                unsigned pr;
                do {
                    asm volatile("ld.volatile.shared.u32 %0, [%1];" : "=r"(pr) : "r"(rprog_a));
                } while ((unsigned)k - pr > 160u);
            }
        }

        // rotate prefetch ring (renamed away under unrolling)
#pragma unroll
        for (int q = 0; q < PF - 1; q++) dd[q] = dd[q + 1];
        dd[PF - 1] = dn;
    };

    int k = 1;
#pragma unroll 1
    for (; k + (PF - 1) <= KK - 1; k += PF) {
#pragma unroll
        for (int u = 0; u < PF; u++) body(k + u);
    }
    for (; k <= KK - 1; ++k) body(k);

    if (rank == 7 && t == 255) g_sdtw[z] = r1;   // r_{K-1}[N-1]

    asm volatile("barrier.cluster.arrive.aligned;" ::: "memory");
    asm volatile("barrier.cluster.wait.aligned;" ::: "memory");
}

// ---------------- combine ----------------
__global__ void finalize_kernel(float* out) {
    float pos = g_sdtw[0] - 0.5f * (g_sdtw[1] + g_sdtw[2]);
    float idm = (float)(g_idm[0] + g_idm[1]);
    out[0] = (pos + idm) / 2048.0f;    // ALPHA = 1, NUM_FRAMES = 2048
}

// ---------------- launch ----------------
extern "C" void kernel_launch(void* const* d_in, const int* in_sizes, int n_in,
                              void* d_out, int out_size) {
    const float* a = (const float*)d_in[0];   // a_emb [1,2048,128] fp32
    const float* b = (const float*)d_in[1];   // b_emb [1,2048,128] fp32
    (void)in_sizes; (void)n_in; (void)out_size;

    norms_kernel<<<512, 256>>>(a, b);
    dim3 g(32, 32, 3);
    pairdist_kernel<<<g, 256>>>(a, b);        // D in diagonal layout + fused idm
    softdtw_kernel<<<24, 256>>>();            // 3 clusters x 8 CTAs, barrier-free wavefronts
    finalize_kernel<<<1, 1>>>((float*)d_out);
}